// round 14
// baseline (speedup 1.0000x reference)
#include <cuda_runtime.h>
#include <cuda_fp16.h>
#include <cstdint>

// Problem dims
#define LL 16
#define TT 2048
#define DD 2048
#define RR 128
#define KK 1024   // tokens routed to s2 (top-k); TT-KK tokens need the s1 GEMM

// ---------------- scratch (device globals: no allocation allowed) ----------------
__device__ float g_hrelu[(size_t)LL * TT * RR];
__device__ float g_logits[LL * TT];
__device__ int   g_copy_idx[LL * KK];
__device__ int   g_comp_idx[LL * KK];
// fp16 hi/lo split operands (22-bit effective mantissa via 2-term split)
__device__ __align__(1024) __half g_hid_hi[(size_t)LL * TT * DD];
__device__ __align__(1024) __half g_hid_lo[(size_t)LL * TT * DD];
__device__ __align__(1024) __half g_wt_hi[(size_t)LL * DD * DD];   // W_s1^T [l,n,k]
__device__ __align__(1024) __half g_wt_lo[(size_t)LL * DD * DD];
__device__ __align__(1024) __half g_wr1_hi[(size_t)LL * RR * DD];  // W_r1^T [l,r,d]
__device__ __align__(1024) __half g_wr1_lo[(size_t)LL * RR * DD];

// ---------------- helpers ----------------
__device__ __forceinline__ uint32_t smem_u32(const void* p) {
    uint32_t a;
    asm("{ .reg .u64 t; cvta.to.shared.u64 t, %1; cvt.u32.u64 %0, t; }" : "=r"(a) : "l"(p));
    return a;
}
__device__ __forceinline__ void cp16(uint32_t s, const void* g) {
    asm volatile("cp.async.cg.shared.global [%0], [%1], 16;" :: "r"(s), "l"(g));
}
#define CP_COMMIT() asm volatile("cp.async.commit_group;" ::: "memory")
#define CP_WAIT(n)  asm volatile("cp.async.wait_group %0;" :: "n"(n) : "memory")

__device__ __forceinline__ void ldsm4(uint32_t* r, uint32_t addr) {
    asm volatile("ldmatrix.sync.aligned.m8n8.x4.shared.b16 {%0,%1,%2,%3}, [%4];"
                 : "=r"(r[0]), "=r"(r[1]), "=r"(r[2]), "=r"(r[3]) : "r"(addr));
}
__device__ __forceinline__ void mma_fp16(float* c, const uint32_t* a,
                                         uint32_t b0, uint32_t b1) {
    asm volatile(
        "mma.sync.aligned.m16n8k16.row.col.f32.f16.f16.f32 "
        "{%0,%1,%2,%3}, {%4,%5,%6,%7}, {%8,%9}, {%0,%1,%2,%3};"
        : "+f"(c[0]), "+f"(c[1]), "+f"(c[2]), "+f"(c[3])
        : "r"(a[0]), "r"(a[1]), "r"(a[2]), "r"(a[3]), "r"(b0), "r"(b1));
}

// =================================================================================
// Conversion kernels (fp32 -> fp16 hi + fp16 lo; a = ah + al + O(2^-22 |a|))
// =================================================================================
__global__ __launch_bounds__(256) void conv_hidden_kernel(const float* __restrict__ hidden) {
    size_t i = ((size_t)blockIdx.x * 256 + threadIdx.x) * 4;
    float4 v = *(const float4*)(hidden + i);
    __half h0 = __float2half_rn(v.x), h1 = __float2half_rn(v.y);
    __half h2 = __float2half_rn(v.z), h3 = __float2half_rn(v.w);
    __half l0 = __float2half_rn(v.x - __half2float(h0));
    __half l1 = __float2half_rn(v.y - __half2float(h1));
    __half l2 = __float2half_rn(v.z - __half2float(h2));
    __half l3 = __float2half_rn(v.w - __half2float(h3));
    __half2 hp0 = __halves2half2(h0, h1), hp1 = __halves2half2(h2, h3);
    __half2 lp0 = __halves2half2(l0, l1), lp1 = __halves2half2(l2, l3);
    uint2 hw, lw;
    hw.x = *(uint32_t*)&hp0; hw.y = *(uint32_t*)&hp1;
    lw.x = *(uint32_t*)&lp0; lw.y = *(uint32_t*)&lp1;
    *(uint2*)(g_hid_hi + i) = hw;
    *(uint2*)(g_hid_lo + i) = lw;
}

// W_s1 [l, k, n] fp32 -> transposed fp16 hi/lo [l, n, k]
__global__ __launch_bounds__(256) void conv_wt_kernel(const float* __restrict__ Ws1) {
    __shared__ float tile[32][33];
    const int l  = blockIdx.z;
    const int kb = blockIdx.y * 32;
    const int nb = blockIdx.x * 32;
    const int x  = threadIdx.x;
    const int ty = threadIdx.y;
    const float* src = Ws1 + (size_t)l * DD * DD;
#pragma unroll
    for (int j = ty; j < 32; j += 8)
        tile[j][x] = src[(size_t)(kb + j) * DD + nb + x];
    __syncthreads();
#pragma unroll
    for (int j = ty; j < 32; j += 8) {
        float v = tile[x][j];   // = W[kb+x, nb+j]
        __half hi = __float2half_rn(v);
        __half lo = __float2half_rn(v - __half2float(hi));
        size_t o = (size_t)l * DD * DD + (size_t)(nb + j) * DD + kb + x;
        g_wt_hi[o] = hi;
        g_wt_lo[o] = lo;
    }
}

// W_r1 [l, d, r] fp32 -> transposed fp16 hi/lo [l, r, d]
__global__ __launch_bounds__(256) void conv_wr1_kernel(const float* __restrict__ Wr1) {
    __shared__ float tile[32][33];
    const int l  = blockIdx.z;
    const int db = blockIdx.y * 32;
    const int rb = blockIdx.x * 32;
    const int x  = threadIdx.x;
    const int ty = threadIdx.y;
    const float* src = Wr1 + (size_t)l * DD * RR;
#pragma unroll
    for (int j = ty; j < 32; j += 8)
        tile[j][x] = src[(size_t)(db + j) * RR + rb + x];
    __syncthreads();
#pragma unroll
    for (int j = ty; j < 32; j += 8) {
        float v = tile[x][j];   // = W[d=db+x, r=rb+j]
        __half hi = __float2half_rn(v);
        __half lo = __float2half_rn(v - __half2float(hi));
        size_t o = (size_t)l * RR * DD + (size_t)(rb + j) * DD + db + x;
        g_wr1_hi[o] = hi;
        g_wr1_lo[o] = lo;
    }
}

// =================================================================================
// Shared HMMA tile machinery: CTA tile 128(M) x 128(N), BK=32, 512 threads,
// 16 warps in 4(M) x 4(N) grid -> 32x32 warp tile (4 warps/SMSP for latency hiding).
// 3-stage cp.async ring, ONE __syncthreads per K-iter (validated R7 pattern).
// Each thread loads exactly one 16B chunk per matrix per stage.
// =================================================================================
#define ROWB   80
#define MATB   (128 * ROWB)      // 10240 B per matrix (64B data + 16B pad per row)
#define STAGEB (4 * MATB)        // A_hi, A_lo, B_hi, B_lo
#define S1_SMEM (1024 + 3 * STAGEB)   // 123904 B

// ---------------------------------------------------------------------------------
// Router hidden GEMM on HMMA: g_hrelu[l,t,r] = relu(hidden@W_r1 + b_r1)
// grid (TT/128=16, LL=16), 512 threads.
// ---------------------------------------------------------------------------------
__global__ __launch_bounds__(512, 1)
void router_mma_kernel(const float* __restrict__ b1) {
    extern __shared__ __align__(128) char smem[];
    const uint32_t sb = smem_u32(smem);
    const int tid  = threadIdx.x;
    const int lane = tid & 31;
    const int wid  = tid >> 5;
    const int mt = blockIdx.x, l = blockIdx.y;

    const int row = tid >> 2, ch = tid & 3;   // one 16B chunk per matrix
    const size_t aoff = ((size_t)l * TT + mt * 128 + row) * DD + ch * 8;
    const __half* pa_hi = g_hid_hi + aoff;
    const __half* pa_lo = g_hid_lo + aoff;
    const size_t boff = ((size_t)l * RR + row) * DD + ch * 8;
    const __half* pb_hi = g_wr1_hi + boff;
    const __half* pb_lo = g_wr1_lo + boff;
    const uint32_t sdst = (uint32_t)(row * ROWB + ch * 16);

    auto load_stage = [&](int buf, int it) {
        const uint32_t base = sb + 1024 + buf * STAGEB;
        const int ko = it * 32;
        cp16(base + 0 * MATB + sdst, pa_hi + ko);
        cp16(base + 1 * MATB + sdst, pa_lo + ko);
        cp16(base + 2 * MATB + sdst, pb_hi + ko);
        cp16(base + 3 * MATB + sdst, pb_lo + ko);
        CP_COMMIT();
    };

    const int warp_m = wid & 3;   // 0..3, 32-row tile
    const int warp_n = wid >> 2;  // 0..3, 32-col tile
    const uint32_t offA = (uint32_t)((warp_m * 32 + (lane & 15)) * ROWB +
                                     ((lane & 16) ? 16 : 0));
    const uint32_t offB = (uint32_t)((warp_n * 32 + (lane & 7) + ((lane & 16) ? 8 : 0)) * ROWB +
                                     ((lane & 8) ? 16 : 0));

    float acc[2][4][4];
#pragma unroll
    for (int i = 0; i < 2; i++)
#pragma unroll
        for (int j = 0; j < 4; j++)
#pragma unroll
            for (int k = 0; k < 4; k++) acc[i][j][k] = 0.f;

    load_stage(0, 0);
    load_stage(1, 1);

    const int NIT = DD / 32;
    int slot = 0;
    for (int it = 0; it < NIT; it++) {
        if (it + 1 < NIT) { CP_WAIT(1); } else { CP_WAIT(0); }
        __syncthreads();
        if (it + 2 < NIT) {
            int ns = slot + 2; if (ns >= 3) ns -= 3;
            load_stage(ns, it + 2);
        }
        const uint32_t base = sb + 1024 + slot * STAGEB;
        const uint32_t Ah = base + 0 * MATB, Al = base + 1 * MATB;
        const uint32_t Bh = base + 2 * MATB, Bl = base + 3 * MATB;
#pragma unroll
        for (int kk = 0; kk < 2; kk++) {
            const uint32_t kof = kk * 32;
            uint32_t ah[2][4], al[2][4], bh[2][4], bl[2][4];
#pragma unroll
            for (int mf = 0; mf < 2; mf++) {
                const uint32_t o = offA + mf * 16 * ROWB + kof;
                ldsm4(ah[mf], Ah + o);
                ldsm4(al[mf], Al + o);
            }
#pragma unroll
            for (int nf2 = 0; nf2 < 2; nf2++) {
                const uint32_t o = offB + nf2 * 16 * ROWB + kof;
                ldsm4(bh[nf2], Bh + o);
                ldsm4(bl[nf2], Bl + o);
            }
#pragma unroll
            for (int mf = 0; mf < 2; mf++) {
#pragma unroll
                for (int nf = 0; nf < 4; nf++) {
                    const int n2 = nf >> 1, s = (nf & 1) * 2;
                    mma_fp16(acc[mf][nf], ah[mf], bh[n2][s], bh[n2][s + 1]);
                    mma_fp16(acc[mf][nf], ah[mf], bl[n2][s], bl[n2][s + 1]);
                    mma_fp16(acc[mf][nf], al[mf], bh[n2][s], bh[n2][s + 1]);
                }
            }
        }
        if (++slot == 3) slot = 0;
    }

    // epilogue: +bias, relu, store fp32 to g_hrelu
    const int g   = lane >> 2;
    const int tig = lane & 3;
#pragma unroll
    for (int mf = 0; mf < 2; mf++) {
        const int m0 = warp_m * 32 + mf * 16 + g;
        float* d0 = g_hrelu + ((size_t)l * TT + mt * 128 + m0) * RR;
        float* d1 = g_hrelu + ((size_t)l * TT + mt * 128 + m0 + 8) * RR;
#pragma unroll
        for (int nf = 0; nf < 4; nf++) {
            const int n = warp_n * 32 + nf * 8 + tig * 2;
            const float2 bv = *(const float2*)(b1 + l * RR + n);
            float2 o0, o1;
            o0.x = fmaxf(acc[mf][nf][0] + bv.x, 0.f);
            o0.y = fmaxf(acc[mf][nf][1] + bv.y, 0.f);
            o1.x = fmaxf(acc[mf][nf][2] + bv.x, 0.f);
            o1.y = fmaxf(acc[mf][nf][3] + bv.y, 0.f);
            *(float2*)(d0 + n) = o0;
            *(float2*)(d1 + n) = o1;
        }
    }
}

// =================================================================================
// logits / topk / copy (unchanged, validated)
// =================================================================================
__global__ void logits_kernel(const float* __restrict__ W2, const float* __restrict__ b2) {
    const int gw   = (blockIdx.x * blockDim.x + threadIdx.x) >> 5;
    const int lane = threadIdx.x & 31;
    const int l = gw >> 11;
    const int t = gw & 2047;
    const float* h = g_hrelu + ((size_t)l * TT + t) * RR;
    const float* w = W2 + l * RR;
    float s = 0.f;
#pragma unroll
    for (int r = 0; r < RR; r += 32) s += h[r + lane] * w[r + lane];
#pragma unroll
    for (int o = 16; o; o >>= 1) s += __shfl_xor_sync(0xffffffffu, s, o);
    if (lane == 0) g_logits[l * TT + t] = s + b2[l];
}

__global__ void topk_kernel() {
    __shared__ unsigned long long keys[2048];
    const int l = blockIdx.x;
    const int tid = threadIdx.x;
    for (int i = tid; i < 2048; i += 1024) {
        float f = g_logits[l * TT + i];
        unsigned u = __float_as_uint(f);
        u = (u & 0x80000000u) ? ~u : (u | 0x80000000u);
        keys[i] = ((unsigned long long)(~u) << 32) | (unsigned)i;
    }
    __syncthreads();
    for (int ks = 2; ks <= 2048; ks <<= 1) {
        for (int j = ks >> 1; j > 0; j >>= 1) {
            for (int i = tid; i < 2048; i += 1024) {
                int ixj = i ^ j;
                if (ixj > i) {
                    unsigned long long a = keys[i], b = keys[ixj];
                    bool asc = ((i & ks) == 0);
                    if ((a > b) == asc) { keys[i] = b; keys[ixj] = a; }
                }
            }
            __syncthreads();
        }
    }
    for (int i = tid; i < 2048; i += 1024) {
        int idx = (int)(keys[i] & 0xFFFFFFFFu);
        if (i < KK) g_copy_idx[l * KK + i]        = idx;
        else        g_comp_idx[l * KK + (i - KK)] = idx;
    }
}

__global__ void copy_s2_kernel(const float* __restrict__ s2, float* __restrict__ out) {
    const int l = blockIdx.y;
    const int t = g_copy_idx[l * KK + blockIdx.x];
    const float4* src = (const float4*)(s2  + ((size_t)l * TT + t) * DD);
    float4*       dst = (float4*)      (out + ((size_t)l * TT + t) * DD);
#pragma unroll
    for (int i = threadIdx.x; i < DD / 4; i += 256) dst[i] = src[i];
}

// =================================================================================
// s1 GEMM (fp16 hi/lo 3-pass), 512 threads, 4x4 warp grid.
// grid (DD/128=16, KK/128=8, LL=16).
// =================================================================================
__global__ __launch_bounds__(512, 1)
void s1_mma_kernel(const float* __restrict__ bs1, float* __restrict__ out) {
    extern __shared__ __align__(128) char smem[];
    const uint32_t sb = smem_u32(smem);
    int* rows_s = (int*)smem;
    const int tid  = threadIdx.x;
    const int lane = tid & 31;
    const int wid  = tid >> 5;
    const int nt = blockIdx.x, mt = blockIdx.y, l = blockIdx.z;

    if (tid < 128) rows_s[tid] = g_comp_idx[l * KK + mt * 128 + tid];
    __syncthreads();

    const int row = tid >> 2, ch = tid & 3;
    const size_t aoff = ((size_t)l * TT + rows_s[row]) * DD + ch * 8;
    const __half* pa_hi = g_hid_hi + aoff;
    const __half* pa_lo = g_hid_lo + aoff;
    const size_t boff = ((size_t)l * DD + nt * 128 + row) * DD + ch * 8;
    const __half* pb_hi = g_wt_hi + boff;
    const __half* pb_lo = g_wt_lo + boff;
    const uint32_t sdst = (uint32_t)(row * ROWB + ch * 16);

    auto load_stage = [&](int buf, int it) {
        const uint32_t base = sb + 1024 + buf * STAGEB;
        const int ko = it * 32;
        cp16(base + 0 * MATB + sdst, pa_hi + ko);
        cp16(base + 1 * MATB + sdst, pa_lo + ko);
        cp16(base + 2 * MATB + sdst, pb_hi + ko);
        cp16(base + 3 * MATB + sdst, pb_lo + ko);
        CP_COMMIT();
    };

    const int warp_m = wid & 3;
    const int warp_n = wid >> 2;
    const uint32_t offA = (uint32_t)((warp_m * 32 + (lane & 15)) * ROWB +
                                     ((lane & 16) ? 16 : 0));
    const uint32_t offB = (uint32_t)((warp_n * 32 + (lane & 7) + ((lane & 16) ? 8 : 0)) * ROWB +
                                     ((lane & 8) ? 16 : 0));

    float acc[2][4][4];
#pragma unroll
    for (int i = 0; i < 2; i++)
#pragma unroll
        for (int j = 0; j < 4; j++)
#pragma unroll
            for (int k = 0; k < 4; k++) acc[i][j][k] = 0.f;

    load_stage(0, 0);
    load_stage(1, 1);

    const int NIT = DD / 32;
    int slot = 0;
    for (int it = 0; it < NIT; it++) {
        if (it + 1 < NIT) { CP_WAIT(1); } else { CP_WAIT(0); }
        __syncthreads();
        if (it + 2 < NIT) {
            int ns = slot + 2; if (ns >= 3) ns -= 3;
            load_stage(ns, it + 2);
        }
        const uint32_t base = sb + 1024 + slot * STAGEB;
        const uint32_t Ah = base + 0 * MATB, Al = base + 1 * MATB;
        const uint32_t Bh = base + 2 * MATB, Bl = base + 3 * MATB;
#pragma unroll
        for (int kk = 0; kk < 2; kk++) {
            const uint32_t kof = kk * 32;
            uint32_t ah[2][4], al[2][4], bh[2][4], bl[2][4];
#pragma unroll
            for (int mf = 0; mf < 2; mf++) {
                const uint32_t o = offA + mf * 16 * ROWB + kof;
                ldsm4(ah[mf], Ah + o);
                ldsm4(al[mf], Al + o);
            }
#pragma unroll
            for (int nf2 = 0; nf2 < 2; nf2++) {
                const uint32_t o = offB + nf2 * 16 * ROWB + kof;
                ldsm4(bh[nf2], Bh + o);
                ldsm4(bl[nf2], Bl + o);
            }
#pragma unroll
            for (int mf = 0; mf < 2; mf++) {
#pragma unroll
                for (int nf = 0; nf < 4; nf++) {
                    const int n2 = nf >> 1, s = (nf & 1) * 2;
                    mma_fp16(acc[mf][nf], ah[mf], bh[n2][s], bh[n2][s + 1]);
                    mma_fp16(acc[mf][nf], ah[mf], bl[n2][s], bl[n2][s + 1]);
                    mma_fp16(acc[mf][nf], al[mf], bh[n2][s], bh[n2][s + 1]);
                }
            }
        }
        if (++slot == 3) slot = 0;
    }

    const int g   = lane >> 2;
    const int tig = lane & 3;
#pragma unroll
    for (int mf = 0; mf < 2; mf++) {
        const int m0 = warp_m * 32 + mf * 16 + g;
        const int r0 = rows_s[m0];
        const int r1 = rows_s[m0 + 8];
        float* d0 = out + ((size_t)l * TT + r0) * DD;
        float* d1 = out + ((size_t)l * TT + r1) * DD;
#pragma unroll
        for (int nf = 0; nf < 4; nf++) {
            const int n = nt * 128 + warp_n * 32 + nf * 8 + tig * 2;
            const float2 bv = *(const float2*)(bs1 + l * DD + n);
            float2 o0, o1;
            o0.x = acc[mf][nf][0] + bv.x; o0.y = acc[mf][nf][1] + bv.y;
            o1.x = acc[mf][nf][2] + bv.x; o1.y = acc[mf][nf][3] + bv.y;
            *(float2*)(d0 + n) = o0;
            *(float2*)(d1 + n) = o1;
        }
    }
}

// =================================================================================
extern "C" void kernel_launch(void* const* d_in, const int* in_sizes, int n_in,
                              void* d_out, int out_size) {
    const float* hidden = (const float*)d_in[0];
    const float* s2     = (const float*)d_in[1];
    const float* W_r1   = (const float*)d_in[2];
    const float* b_r1   = (const float*)d_in[3];
    const float* W_r2   = (const float*)d_in[4];
    const float* b_r2   = (const float*)d_in[5];
    const float* W_s1   = (const float*)d_in[6];
    const float* b_s1   = (const float*)d_in[7];
    float* out = (float*)d_out;

    static cudaStream_t sB = nullptr;
    static cudaEvent_t e0, eB, eT, eC;
    static bool init_done = false;
    if (!init_done) {
        cudaFuncSetAttribute(s1_mma_kernel,
                             cudaFuncAttributeMaxDynamicSharedMemorySize, S1_SMEM);
        cudaFuncSetAttribute(router_mma_kernel,
                             cudaFuncAttributeMaxDynamicSharedMemorySize, S1_SMEM);
        cudaStreamCreateWithFlags(&sB, cudaStreamNonBlocking);
        cudaEventCreateWithFlags(&e0, cudaEventDisableTiming);
        cudaEventCreateWithFlags(&eB, cudaEventDisableTiming);
        cudaEventCreateWithFlags(&eT, cudaEventDisableTiming);
        cudaEventCreateWithFlags(&eC, cudaEventDisableTiming);
        init_done = true;
    }

    // main stream: hidden split (needed by both branches)
    conv_hidden_kernel<<<(LL * TT * (DD / 4)) / 256, 256>>>(hidden);
    cudaEventRecord(e0, 0);

    // branch B: W_s1 transpose+split (only needed by s1)
    cudaStreamWaitEvent(sB, e0, 0);
    conv_wt_kernel<<<dim3(DD / 32, DD / 32, LL), dim3(32, 8), 0, sB>>>(W_s1);
    cudaEventRecord(eB, sB);

    // main stream: router chain
    conv_wr1_kernel<<<dim3(RR / 32, DD / 32, LL), dim3(32, 8)>>>(W_r1);
    router_mma_kernel<<<dim3(TT / 128, LL), 512, S1_SMEM>>>(b_r1);
    logits_kernel<<<(LL * TT) / 8, 256>>>(W_r2, b_r2);
    topk_kernel<<<LL, 1024>>>();
    cudaEventRecord(eT, 0);

    // branch B: copy top-K rows (needs topk only), overlapped with s1
    cudaStreamWaitEvent(sB, eT, 0);
    copy_s2_kernel<<<dim3(KK, LL), 256, 0, sB>>>(s2, out);
    cudaEventRecord(eC, sB);

    // main stream: s1 GEMM (needs conv_wt + topk)
    cudaStreamWaitEvent(0, eB, 0);
    dim3 g2(DD / 128, KK / 128, LL);
    s1_mma_kernel<<<g2, 512, S1_SMEM>>>(b_s1, out);
    cudaStreamWaitEvent(0, eC, 0);   // join copy branch
}

// round 16
// speedup vs baseline: 1.2940x; 1.2940x over previous
#include <cuda_runtime.h>
#include <cuda_fp16.h>
#include <cstdint>

// Problem dims
#define LL 16
#define TT 2048
#define DD 2048
#define RR 128
#define KK 1024   // tokens routed to s2 (top-k); TT-KK tokens need the s1 GEMM

// ---------------- scratch (device globals: no allocation allowed) ----------------
__device__ float g_hrelu[(size_t)LL * TT * RR];
__device__ float g_logits[LL * TT];
__device__ int   g_copy_idx[LL * KK];
__device__ int   g_comp_idx[LL * KK];
// fp16 hi/lo split operands (22-bit effective mantissa via 2-term split)
__device__ __align__(1024) __half g_hid_hi[(size_t)LL * TT * DD];
__device__ __align__(1024) __half g_hid_lo[(size_t)LL * TT * DD];
__device__ __align__(1024) __half g_wt_hi[(size_t)LL * DD * DD];   // W_s1^T [l,n,k]
__device__ __align__(1024) __half g_wt_lo[(size_t)LL * DD * DD];
__device__ __align__(1024) __half g_wr1_hi[(size_t)LL * RR * DD];  // W_r1^T [l,r,d]
__device__ __align__(1024) __half g_wr1_lo[(size_t)LL * RR * DD];

// ---------------- helpers ----------------
__device__ __forceinline__ uint32_t smem_u32(const void* p) {
    uint32_t a;
    asm("{ .reg .u64 t; cvta.to.shared.u64 t, %1; cvt.u32.u64 %0, t; }" : "=r"(a) : "l"(p));
    return a;
}
__device__ __forceinline__ void cp16(uint32_t s, const void* g) {
    asm volatile("cp.async.cg.shared.global [%0], [%1], 16;" :: "r"(s), "l"(g));
}
#define CP_COMMIT() asm volatile("cp.async.commit_group;" ::: "memory")
#define CP_WAIT(n)  asm volatile("cp.async.wait_group %0;" :: "n"(n) : "memory")

__device__ __forceinline__ void ldsm4(uint32_t* r, uint32_t addr) {
    asm volatile("ldmatrix.sync.aligned.m8n8.x4.shared.b16 {%0,%1,%2,%3}, [%4];"
                 : "=r"(r[0]), "=r"(r[1]), "=r"(r[2]), "=r"(r[3]) : "r"(addr));
}
__device__ __forceinline__ void mma_fp16(float* c, const uint32_t* a,
                                         uint32_t b0, uint32_t b1) {
    asm volatile(
        "mma.sync.aligned.m16n8k16.row.col.f32.f16.f16.f32 "
        "{%0,%1,%2,%3}, {%4,%5,%6,%7}, {%8,%9}, {%0,%1,%2,%3};"
        : "+f"(c[0]), "+f"(c[1]), "+f"(c[2]), "+f"(c[3])
        : "r"(a[0]), "r"(a[1]), "r"(a[2]), "r"(a[3]), "r"(b0), "r"(b1));
}

// =================================================================================
// Conversion kernels (fp32 -> fp16 hi + fp16 lo; a = ah + al + O(2^-22 |a|))
// =================================================================================
__global__ __launch_bounds__(256) void conv_hidden_kernel(const float* __restrict__ hidden) {
    size_t i = ((size_t)blockIdx.x * 256 + threadIdx.x) * 4;
    float4 v = *(const float4*)(hidden + i);
    __half h0 = __float2half_rn(v.x), h1 = __float2half_rn(v.y);
    __half h2 = __float2half_rn(v.z), h3 = __float2half_rn(v.w);
    __half l0 = __float2half_rn(v.x - __half2float(h0));
    __half l1 = __float2half_rn(v.y - __half2float(h1));
    __half l2 = __float2half_rn(v.z - __half2float(h2));
    __half l3 = __float2half_rn(v.w - __half2float(h3));
    __half2 hp0 = __halves2half2(h0, h1), hp1 = __halves2half2(h2, h3);
    __half2 lp0 = __halves2half2(l0, l1), lp1 = __halves2half2(l2, l3);
    uint2 hw, lw;
    hw.x = *(uint32_t*)&hp0; hw.y = *(uint32_t*)&hp1;
    lw.x = *(uint32_t*)&lp0; lw.y = *(uint32_t*)&lp1;
    *(uint2*)(g_hid_hi + i) = hw;
    *(uint2*)(g_hid_lo + i) = lw;
}

// W_s1 [l, k, n] fp32 -> transposed fp16 hi/lo [l, n, k]
__global__ __launch_bounds__(256) void conv_wt_kernel(const float* __restrict__ Ws1) {
    __shared__ float tile[32][33];
    const int l  = blockIdx.z;
    const int kb = blockIdx.y * 32;
    const int nb = blockIdx.x * 32;
    const int x  = threadIdx.x;
    const int ty = threadIdx.y;
    const float* src = Ws1 + (size_t)l * DD * DD;
#pragma unroll
    for (int j = ty; j < 32; j += 8)
        tile[j][x] = src[(size_t)(kb + j) * DD + nb + x];
    __syncthreads();
#pragma unroll
    for (int j = ty; j < 32; j += 8) {
        float v = tile[x][j];   // = W[kb+x, nb+j]
        __half hi = __float2half_rn(v);
        __half lo = __float2half_rn(v - __half2float(hi));
        size_t o = (size_t)l * DD * DD + (size_t)(nb + j) * DD + kb + x;
        g_wt_hi[o] = hi;
        g_wt_lo[o] = lo;
    }
}

// W_r1 [l, d, r] fp32 -> transposed fp16 hi/lo [l, r, d]
__global__ __launch_bounds__(256) void conv_wr1_kernel(const float* __restrict__ Wr1) {
    __shared__ float tile[32][33];
    const int l  = blockIdx.z;
    const int db = blockIdx.y * 32;
    const int rb = blockIdx.x * 32;
    const int x  = threadIdx.x;
    const int ty = threadIdx.y;
    const float* src = Wr1 + (size_t)l * DD * RR;
#pragma unroll
    for (int j = ty; j < 32; j += 8)
        tile[j][x] = src[(size_t)(db + j) * RR + rb + x];
    __syncthreads();
#pragma unroll
    for (int j = ty; j < 32; j += 8) {
        float v = tile[x][j];   // = W[d=db+x, r=rb+j]
        __half hi = __float2half_rn(v);
        __half lo = __float2half_rn(v - __half2float(hi));
        size_t o = (size_t)l * RR * DD + (size_t)(rb + j) * DD + db + x;
        g_wr1_hi[o] = hi;
        g_wr1_lo[o] = lo;
    }
}

// =================================================================================
// HMMA tile machinery (R11 validated geometry): CTA 128x128, BK=32, 256 threads,
// 8 warps (2M x 4N) -> 64x32 warp tile. 3-stage cp.async ring, ONE sync per K-iter.
// =================================================================================
#define ROWB   80
#define MATB   (128 * ROWB)            // 10240 B per matrix
#define RT_STAGEB (4 * MATB)           // router: A_hi, A_lo, B_hi, B_lo (3-pass)
#define RT_SMEM (1024 + 3 * RT_STAGEB) // 123904 B
#define S1_STAGEB (3 * MATB)           // s1: A_hi, B_hi, B_lo (2-pass, no A_lo)
#define S1_SMEM (1024 + 3 * S1_STAGEB) // 93184 B

// ---------------------------------------------------------------------------------
// Router hidden GEMM (3-pass fp16 hi/lo — routing must track reference logits)
// grid (TT/128=16, LL=16), 256 threads.
// ---------------------------------------------------------------------------------
__global__ __launch_bounds__(256, 1)
void router_mma_kernel(const float* __restrict__ b1) {
    extern __shared__ __align__(128) char smem[];
    const uint32_t sb = smem_u32(smem);
    const int tid  = threadIdx.x;
    const int lane = tid & 31;
    const int wid  = tid >> 5;
    const int mt = blockIdx.x, l = blockIdx.y;

    const __half *pa_hi[2], *pa_lo[2], *pb_hi[2], *pb_lo[2];
    uint32_t sdst[2];
#pragma unroll
    for (int q = 0; q < 2; q++) {
        const int c   = tid + q * 256;
        const int row = c >> 2, ch = c & 3;
        const size_t aoff = ((size_t)l * TT + mt * 128 + row) * DD + ch * 8;
        pa_hi[q] = g_hid_hi + aoff;
        pa_lo[q] = g_hid_lo + aoff;
        const size_t boff = ((size_t)l * RR + row) * DD + ch * 8;
        pb_hi[q] = g_wr1_hi + boff;
        pb_lo[q] = g_wr1_lo + boff;
        sdst[q] = (uint32_t)(row * ROWB + ch * 16);
    }

    auto load_stage = [&](int buf, int it) {
        const uint32_t base = sb + 1024 + buf * RT_STAGEB;
        const int ko = it * 32;
#pragma unroll
        for (int q = 0; q < 2; q++) {
            cp16(base + 0 * MATB + sdst[q], pa_hi[q] + ko);
            cp16(base + 1 * MATB + sdst[q], pa_lo[q] + ko);
            cp16(base + 2 * MATB + sdst[q], pb_hi[q] + ko);
            cp16(base + 3 * MATB + sdst[q], pb_lo[q] + ko);
        }
        CP_COMMIT();
    };

    const int warp_m = wid & 1;
    const int warp_n = wid >> 1;
    const uint32_t offA = (uint32_t)((warp_m * 64 + (lane & 15)) * ROWB +
                                     ((lane & 16) ? 16 : 0));
    const uint32_t offB = (uint32_t)((warp_n * 32 + (lane & 7) + ((lane & 16) ? 8 : 0)) * ROWB +
                                     ((lane & 8) ? 16 : 0));

    float acc[4][4][4];
#pragma unroll
    for (int i = 0; i < 4; i++)
#pragma unroll
        for (int j = 0; j < 4; j++)
#pragma unroll
            for (int k = 0; k < 4; k++) acc[i][j][k] = 0.f;

    load_stage(0, 0);
    load_stage(1, 1);

    const int NIT = DD / 32;
    int slot = 0;
    for (int it = 0; it < NIT; it++) {
        if (it + 1 < NIT) { CP_WAIT(1); } else { CP_WAIT(0); }
        __syncthreads();
        if (it + 2 < NIT) {
            int ns = slot + 2; if (ns >= 3) ns -= 3;
            load_stage(ns, it + 2);
        }
        const uint32_t base = sb + 1024 + slot * RT_STAGEB;
        const uint32_t Ah = base + 0 * MATB, Al = base + 1 * MATB;
        const uint32_t Bh = base + 2 * MATB, Bl = base + 3 * MATB;
#pragma unroll
        for (int kk = 0; kk < 2; kk++) {
            const uint32_t kof = kk * 32;
            uint32_t ah[4][4], al[4][4], bh[2][4], bl[2][4];
#pragma unroll
            for (int mf = 0; mf < 4; mf++) {
                const uint32_t o = offA + mf * 16 * ROWB + kof;
                ldsm4(ah[mf], Ah + o);
                ldsm4(al[mf], Al + o);
            }
#pragma unroll
            for (int nf2 = 0; nf2 < 2; nf2++) {
                const uint32_t o = offB + nf2 * 16 * ROWB + kof;
                ldsm4(bh[nf2], Bh + o);
                ldsm4(bl[nf2], Bl + o);
            }
#pragma unroll
            for (int mf = 0; mf < 4; mf++) {
#pragma unroll
                for (int nf = 0; nf < 4; nf++) {
                    const int n2 = nf >> 1, s = (nf & 1) * 2;
                    mma_fp16(acc[mf][nf], ah[mf], bh[n2][s], bh[n2][s + 1]);
                    mma_fp16(acc[mf][nf], ah[mf], bl[n2][s], bl[n2][s + 1]);
                    mma_fp16(acc[mf][nf], al[mf], bh[n2][s], bh[n2][s + 1]);
                }
            }
        }
        if (++slot == 3) slot = 0;
    }

    // epilogue: +bias, relu, store fp32 to g_hrelu
    const int g   = lane >> 2;
    const int tig = lane & 3;
#pragma unroll
    for (int mf = 0; mf < 4; mf++) {
        const int m0 = warp_m * 64 + mf * 16 + g;
        float* d0 = g_hrelu + ((size_t)l * TT + mt * 128 + m0) * RR;
        float* d1 = g_hrelu + ((size_t)l * TT + mt * 128 + m0 + 8) * RR;
#pragma unroll
        for (int nf = 0; nf < 4; nf++) {
            const int n = warp_n * 32 + nf * 8 + tig * 2;
            const float2 bv = *(const float2*)(b1 + l * RR + n);
            float2 o0, o1;
            o0.x = fmaxf(acc[mf][nf][0] + bv.x, 0.f);
            o0.y = fmaxf(acc[mf][nf][1] + bv.y, 0.f);
            o1.x = fmaxf(acc[mf][nf][2] + bv.x, 0.f);
            o1.y = fmaxf(acc[mf][nf][3] + bv.y, 0.f);
            *(float2*)(d0 + n) = o0;
            *(float2*)(d1 + n) = o1;
        }
    }
}

// =================================================================================
// logits / topk / copy (unchanged, validated)
// =================================================================================
__global__ void logits_kernel(const float* __restrict__ W2, const float* __restrict__ b2) {
    const int gw   = (blockIdx.x * blockDim.x + threadIdx.x) >> 5;
    const int lane = threadIdx.x & 31;
    const int l = gw >> 11;
    const int t = gw & 2047;
    const float* h = g_hrelu + ((size_t)l * TT + t) * RR;
    const float* w = W2 + l * RR;
    float s = 0.f;
#pragma unroll
    for (int r = 0; r < RR; r += 32) s += h[r + lane] * w[r + lane];
#pragma unroll
    for (int o = 16; o; o >>= 1) s += __shfl_xor_sync(0xffffffffu, s, o);
    if (lane == 0) g_logits[l * TT + t] = s + b2[l];
}

__global__ void topk_kernel() {
    __shared__ unsigned long long keys[2048];
    const int l = blockIdx.x;
    const int tid = threadIdx.x;
    for (int i = tid; i < 2048; i += 1024) {
        float f = g_logits[l * TT + i];
        unsigned u = __float_as_uint(f);
        u = (u & 0x80000000u) ? ~u : (u | 0x80000000u);
        keys[i] = ((unsigned long long)(~u) << 32) | (unsigned)i;
    }
    __syncthreads();
    for (int ks = 2; ks <= 2048; ks <<= 1) {
        for (int j = ks >> 1; j > 0; j >>= 1) {
            for (int i = tid; i < 2048; i += 1024) {
                int ixj = i ^ j;
                if (ixj > i) {
                    unsigned long long a = keys[i], b = keys[ixj];
                    bool asc = ((i & ks) == 0);
                    if ((a > b) == asc) { keys[i] = b; keys[ixj] = a; }
                }
            }
            __syncthreads();
        }
    }
    for (int i = tid; i < 2048; i += 1024) {
        int idx = (int)(keys[i] & 0xFFFFFFFFu);
        if (i < KK) g_copy_idx[l * KK + i]        = idx;
        else        g_comp_idx[l * KK + (i - KK)] = idx;
    }
}

__global__ void copy_s2_kernel(const float* __restrict__ s2, float* __restrict__ out) {
    const int l = blockIdx.y;
    const int t = g_copy_idx[l * KK + blockIdx.x];
    const float4* src = (const float4*)(s2  + ((size_t)l * TT + t) * DD);
    float4*       dst = (float4*)      (out + ((size_t)l * TT + t) * DD);
#pragma unroll
    for (int i = threadIdx.x; i < DD / 4; i += 256) dst[i] = src[i];
}

// =================================================================================
// s1 GEMM: 2-pass fp16 split, out = ah*(bh+bl); al dropped (err ~1e-4 << 1e-3).
// No A_lo loads: 3 matrices per stage. grid (DD/128=16, KK/128=8, LL=16), 256 thr.
// =================================================================================
__global__ __launch_bounds__(256, 1)
void s1_mma_kernel(const float* __restrict__ bs1, float* __restrict__ out) {
    extern __shared__ __align__(128) char smem[];
    const uint32_t sb = smem_u32(smem);
    int* rows_s = (int*)smem;
    const int tid  = threadIdx.x;
    const int lane = tid & 31;
    const int wid  = tid >> 5;
    const int nt = blockIdx.x, mt = blockIdx.y, l = blockIdx.z;

    if (tid < 128) rows_s[tid] = g_comp_idx[l * KK + mt * 128 + tid];
    __syncthreads();

    const __half *pa_hi[2], *pb_hi[2], *pb_lo[2];
    uint32_t sdst[2];
#pragma unroll
    for (int q = 0; q < 2; q++) {
        const int c   = tid + q * 256;
        const int row = c >> 2, ch = c & 3;
        const size_t aoff = ((size_t)l * TT + rows_s[row]) * DD + ch * 8;
        pa_hi[q] = g_hid_hi + aoff;
        const size_t boff = ((size_t)l * DD + nt * 128 + row) * DD + ch * 8;
        pb_hi[q] = g_wt_hi + boff;
        pb_lo[q] = g_wt_lo + boff;
        sdst[q] = (uint32_t)(row * ROWB + ch * 16);
    }

    auto load_stage = [&](int buf, int it) {
        const uint32_t base = sb + 1024 + buf * S1_STAGEB;
        const int ko = it * 32;
#pragma unroll
        for (int q = 0; q < 2; q++) {
            cp16(base + 0 * MATB + sdst[q], pa_hi[q] + ko);
            cp16(base + 1 * MATB + sdst[q], pb_hi[q] + ko);
            cp16(base + 2 * MATB + sdst[q], pb_lo[q] + ko);
        }
        CP_COMMIT();
    };

    const int warp_m = wid & 1;
    const int warp_n = wid >> 1;
    const uint32_t offA = (uint32_t)((warp_m * 64 + (lane & 15)) * ROWB +
                                     ((lane & 16) ? 16 : 0));
    const uint32_t offB = (uint32_t)((warp_n * 32 + (lane & 7) + ((lane & 16) ? 8 : 0)) * ROWB +
                                     ((lane & 8) ? 16 : 0));

    float acc[4][4][4];
#pragma unroll
    for (int i = 0; i < 4; i++)
#pragma unroll
        for (int j = 0; j < 4; j++)
#pragma unroll
            for (int k = 0; k < 4; k++) acc[i][j][k] = 0.f;

    load_stage(0, 0);
    load_stage(1, 1);

    const int NIT = DD / 32;
    int slot = 0;
    for (int it = 0; it < NIT; it++) {
        if (it + 1 < NIT) { CP_WAIT(1); } else { CP_WAIT(0); }
        __syncthreads();
        if (it + 2 < NIT) {
            int ns = slot + 2; if (ns >= 3) ns -= 3;
            load_stage(ns, it + 2);
        }
        const uint32_t base = sb + 1024 + slot * S1_STAGEB;
        const uint32_t Ah = base + 0 * MATB;
        const uint32_t Bh = base + 1 * MATB, Bl = base + 2 * MATB;
#pragma unroll
        for (int kk = 0; kk < 2; kk++) {
            const uint32_t kof = kk * 32;
            uint32_t ah[4][4], bh[2][4], bl[2][4];
#pragma unroll
            for (int mf = 0; mf < 4; mf++)
                ldsm4(ah[mf], Ah + offA + mf * 16 * ROWB + kof);
#pragma unroll
            for (int nf2 = 0; nf2 < 2; nf2++) {
                const uint32_t o = offB + nf2 * 16 * ROWB + kof;
                ldsm4(bh[nf2], Bh + o);
                ldsm4(bl[nf2], Bl + o);
            }
#pragma unroll
            for (int mf = 0; mf < 4; mf++) {
#pragma unroll
                for (int nf = 0; nf < 4; nf++) {
                    const int n2 = nf >> 1, s = (nf & 1) * 2;
                    mma_fp16(acc[mf][nf], ah[mf], bh[n2][s], bh[n2][s + 1]);
                    mma_fp16(acc[mf][nf], ah[mf], bl[n2][s], bl[n2][s + 1]);
                }
            }
        }
        if (++slot == 3) slot = 0;
    }

    const int g   = lane >> 2;
    const int tig = lane & 3;
#pragma unroll
    for (int mf = 0; mf < 4; mf++) {
        const int m0 = warp_m * 64 + mf * 16 + g;
        const int r0 = rows_s[m0];
        const int r1 = rows_s[m0 + 8];
        float* d0 = out + ((size_t)l * TT + r0) * DD;
        float* d1 = out + ((size_t)l * TT + r1) * DD;
#pragma unroll
        for (int nf = 0; nf < 4; nf++) {
            const int n = nt * 128 + warp_n * 32 + nf * 8 + tig * 2;
            const float2 bv = *(const float2*)(bs1 + l * DD + n);
            float2 o0, o1;
            o0.x = acc[mf][nf][0] + bv.x; o0.y = acc[mf][nf][1] + bv.y;
            o1.x = acc[mf][nf][2] + bv.x; o1.y = acc[mf][nf][3] + bv.y;
            *(float2*)(d0 + n) = o0;
            *(float2*)(d1 + n) = o1;
        }
    }
}

// =================================================================================
extern "C" void kernel_launch(void* const* d_in, const int* in_sizes, int n_in,
                              void* d_out, int out_size) {
    const float* hidden = (const float*)d_in[0];
    const float* s2     = (const float*)d_in[1];
    const float* W_r1   = (const float*)d_in[2];
    const float* b_r1   = (const float*)d_in[3];
    const float* W_r2   = (const float*)d_in[4];
    const float* b_r2   = (const float*)d_in[5];
    const float* W_s1   = (const float*)d_in[6];
    const float* b_s1   = (const float*)d_in[7];
    float* out = (float*)d_out;

    static cudaStream_t sB = nullptr;
    static cudaEvent_t e0, eB, eT, eC;
    static bool init_done = false;
    if (!init_done) {
        cudaFuncSetAttribute(s1_mma_kernel,
                             cudaFuncAttributeMaxDynamicSharedMemorySize, S1_SMEM);
        cudaFuncSetAttribute(router_mma_kernel,
                             cudaFuncAttributeMaxDynamicSharedMemorySize, RT_SMEM);
        cudaStreamCreateWithFlags(&sB, cudaStreamNonBlocking);
        cudaEventCreateWithFlags(&e0, cudaEventDisableTiming);
        cudaEventCreateWithFlags(&eB, cudaEventDisableTiming);
        cudaEventCreateWithFlags(&eT, cudaEventDisableTiming);
        cudaEventCreateWithFlags(&eC, cudaEventDisableTiming);
        init_done = true;
    }

    // main stream: hidden split (needed by both branches)
    conv_hidden_kernel<<<(LL * TT * (DD / 4)) / 256, 256>>>(hidden);
    cudaEventRecord(e0, 0);

    // branch B: W_s1 transpose+split (only needed by s1)
    cudaStreamWaitEvent(sB, e0, 0);
    conv_wt_kernel<<<dim3(DD / 32, DD / 32, LL), dim3(32, 8), 0, sB>>>(W_s1);
    cudaEventRecord(eB, sB);

    // main stream: router chain
    conv_wr1_kernel<<<dim3(RR / 32, DD / 32, LL), dim3(32, 8)>>>(W_r1);
    router_mma_kernel<<<dim3(TT / 128, LL), 256, RT_SMEM>>>(b_r1);
    logits_kernel<<<(LL * TT) / 8, 256>>>(W_r2, b_r2);
    topk_kernel<<<LL, 1024>>>();
    cudaEventRecord(eT, 0);

    // branch B: copy top-K rows (needs topk only), overlapped with s1
    cudaStreamWaitEvent(sB, eT, 0);
    copy_s2_kernel<<<dim3(KK, LL), 256, 0, sB>>>(s2, out);
    cudaEventRecord(eC, sB);

    // main stream: s1 GEMM (needs conv_wt + topk)
    cudaStreamWaitEvent(0, eB, 0);
    dim3 g2(DD / 128, KK / 128, LL);
    s1_mma_kernel<<<g2, 256, S1_SMEM>>>(b_s1, out);
    cudaStreamWaitEvent(0, eC, 0);   // join copy branch
}

// round 17
// speedup vs baseline: 1.7230x; 1.3315x over previous
#include <cuda_runtime.h>
#include <cuda_fp16.h>
#include <cstdint>

// Problem dims
#define LL 16
#define TT 2048
#define DD 2048
#define RR 128
#define KK 1024   // tokens routed to s2 (top-k); TT-KK tokens need the s1 GEMM

// ---------------- scratch (device globals: no allocation allowed) ----------------
__device__ float g_hrelu[(size_t)LL * TT * RR];
__device__ float g_logits[LL * TT];
__device__ int   g_copy_idx[LL * KK];
__device__ int   g_comp_idx[LL * KK];
// fp16 hi/lo split operands (22-bit effective mantissa via 2-term split)
__device__ __align__(1024) __half g_hid_hi[(size_t)LL * TT * DD];
__device__ __align__(1024) __half g_hid_lo[(size_t)LL * TT * DD];
__device__ __align__(1024) __half g_wt_hi[(size_t)LL * DD * DD];   // W_s1^T [l,n,k]
__device__ __align__(1024) __half g_wr1_hi[(size_t)LL * RR * DD];  // W_r1^T [l,r,d]
__device__ __align__(1024) __half g_wr1_lo[(size_t)LL * RR * DD];

// ---------------- helpers ----------------
__device__ __forceinline__ uint32_t smem_u32(const void* p) {
    uint32_t a;
    asm("{ .reg .u64 t; cvta.to.shared.u64 t, %1; cvt.u32.u64 %0, t; }" : "=r"(a) : "l"(p));
    return a;
}
__device__ __forceinline__ void cp16(uint32_t s, const void* g) {
    asm volatile("cp.async.cg.shared.global [%0], [%1], 16;" :: "r"(s), "l"(g));
}
#define CP_COMMIT() asm volatile("cp.async.commit_group;" ::: "memory")
#define CP_WAIT(n)  asm volatile("cp.async.wait_group %0;" :: "n"(n) : "memory")

__device__ __forceinline__ void ldsm4(uint32_t* r, uint32_t addr) {
    asm volatile("ldmatrix.sync.aligned.m8n8.x4.shared.b16 {%0,%1,%2,%3}, [%4];"
                 : "=r"(r[0]), "=r"(r[1]), "=r"(r[2]), "=r"(r[3]) : "r"(addr));
}
__device__ __forceinline__ void mma_fp16(float* c, const uint32_t* a,
                                         uint32_t b0, uint32_t b1) {
    asm volatile(
        "mma.sync.aligned.m16n8k16.row.col.f32.f16.f16.f32 "
        "{%0,%1,%2,%3}, {%4,%5,%6,%7}, {%8,%9}, {%0,%1,%2,%3};"
        : "+f"(c[0]), "+f"(c[1]), "+f"(c[2]), "+f"(c[3])
        : "r"(a[0]), "r"(a[1]), "r"(a[2]), "r"(a[3]), "r"(b0), "r"(b1));
}

// =================================================================================
// Conversion kernels (fp32 -> fp16 hi + fp16 lo; a = ah + al + O(2^-22 |a|))
// =================================================================================
__global__ __launch_bounds__(256) void conv_hidden_kernel(const float* __restrict__ hidden) {
    size_t i = ((size_t)blockIdx.x * 256 + threadIdx.x) * 4;
    float4 v = *(const float4*)(hidden + i);
    __half h0 = __float2half_rn(v.x), h1 = __float2half_rn(v.y);
    __half h2 = __float2half_rn(v.z), h3 = __float2half_rn(v.w);
    __half l0 = __float2half_rn(v.x - __half2float(h0));
    __half l1 = __float2half_rn(v.y - __half2float(h1));
    __half l2 = __float2half_rn(v.z - __half2float(h2));
    __half l3 = __float2half_rn(v.w - __half2float(h3));
    __half2 hp0 = __halves2half2(h0, h1), hp1 = __halves2half2(h2, h3);
    __half2 lp0 = __halves2half2(l0, l1), lp1 = __halves2half2(l2, l3);
    uint2 hw, lw;
    hw.x = *(uint32_t*)&hp0; hw.y = *(uint32_t*)&hp1;
    lw.x = *(uint32_t*)&lp0; lw.y = *(uint32_t*)&lp1;
    *(uint2*)(g_hid_hi + i) = hw;
    *(uint2*)(g_hid_lo + i) = lw;
}

// W_s1 [l, k, n] fp32 -> transposed fp16 hi only [l, n, k] (s1 is 1-pass now)
__global__ __launch_bounds__(256) void conv_wt_kernel(const float* __restrict__ Ws1) {
    __shared__ float tile[32][33];
    const int l  = blockIdx.z;
    const int kb = blockIdx.y * 32;
    const int nb = blockIdx.x * 32;
    const int x  = threadIdx.x;
    const int ty = threadIdx.y;
    const float* src = Ws1 + (size_t)l * DD * DD;
#pragma unroll
    for (int j = ty; j < 32; j += 8)
        tile[j][x] = src[(size_t)(kb + j) * DD + nb + x];
    __syncthreads();
#pragma unroll
    for (int j = ty; j < 32; j += 8) {
        float v = tile[x][j];   // = W[kb+x, nb+j]
        size_t o = (size_t)l * DD * DD + (size_t)(nb + j) * DD + kb + x;
        g_wt_hi[o] = __float2half_rn(v);
    }
}

// W_r1 [l, d, r] fp32 -> transposed fp16 hi/lo [l, r, d]
__global__ __launch_bounds__(256) void conv_wr1_kernel(const float* __restrict__ Wr1) {
    __shared__ float tile[32][33];
    const int l  = blockIdx.z;
    const int db = blockIdx.y * 32;
    const int rb = blockIdx.x * 32;
    const int x  = threadIdx.x;
    const int ty = threadIdx.y;
    const float* src = Wr1 + (size_t)l * DD * RR;
#pragma unroll
    for (int j = ty; j < 32; j += 8)
        tile[j][x] = src[(size_t)(db + j) * RR + rb + x];
    __syncthreads();
#pragma unroll
    for (int j = ty; j < 32; j += 8) {
        float v = tile[x][j];   // = W[d=db+x, r=rb+j]
        __half hi = __float2half_rn(v);
        __half lo = __float2half_rn(v - __half2float(hi));
        size_t o = (size_t)l * RR * DD + (size_t)(rb + j) * DD + db + x;
        g_wr1_hi[o] = hi;
        g_wr1_lo[o] = lo;
    }
}

// =================================================================================
// HMMA tile machinery (validated geometry): CTA 128x128, BK=32, 256 threads,
// 8 warps (2M x 4N) -> 64x32 warp tile. 3-stage cp.async ring, ONE sync per K-iter.
// =================================================================================
#define ROWB   80
#define MATB   (128 * ROWB)            // 10240 B per matrix
#define RT_STAGEB (4 * MATB)           // router: A_hi, A_lo, B_hi, B_lo (3-pass)
#define RT_SMEM (1024 + 3 * RT_STAGEB) // 123904 B
#define S1_STAGEB (2 * MATB)           // s1: A_hi, B_hi (1-pass)
#define S1_SMEM (1024 + 3 * S1_STAGEB) // 62464 B

// ---------------------------------------------------------------------------------
// Router hidden GEMM (3-pass fp16 hi/lo — routing must track reference logits)
// grid (TT/128=16, LL=16), 256 threads.
// ---------------------------------------------------------------------------------
__global__ __launch_bounds__(256, 1)
void router_mma_kernel(const float* __restrict__ b1) {
    extern __shared__ __align__(128) char smem[];
    const uint32_t sb = smem_u32(smem);
    const int tid  = threadIdx.x;
    const int lane = tid & 31;
    const int wid  = tid >> 5;
    const int mt = blockIdx.x, l = blockIdx.y;

    const __half *pa_hi[2], *pa_lo[2], *pb_hi[2], *pb_lo[2];
    uint32_t sdst[2];
#pragma unroll
    for (int q = 0; q < 2; q++) {
        const int c   = tid + q * 256;
        const int row = c >> 2, ch = c & 3;
        const size_t aoff = ((size_t)l * TT + mt * 128 + row) * DD + ch * 8;
        pa_hi[q] = g_hid_hi + aoff;
        pa_lo[q] = g_hid_lo + aoff;
        const size_t boff = ((size_t)l * RR + row) * DD + ch * 8;
        pb_hi[q] = g_wr1_hi + boff;
        pb_lo[q] = g_wr1_lo + boff;
        sdst[q] = (uint32_t)(row * ROWB + ch * 16);
    }

    auto load_stage = [&](int buf, int it) {
        const uint32_t base = sb + 1024 + buf * RT_STAGEB;
        const int ko = it * 32;
#pragma unroll
        for (int q = 0; q < 2; q++) {
            cp16(base + 0 * MATB + sdst[q], pa_hi[q] + ko);
            cp16(base + 1 * MATB + sdst[q], pa_lo[q] + ko);
            cp16(base + 2 * MATB + sdst[q], pb_hi[q] + ko);
            cp16(base + 3 * MATB + sdst[q], pb_lo[q] + ko);
        }
        CP_COMMIT();
    };

    const int warp_m = wid & 1;
    const int warp_n = wid >> 1;
    const uint32_t offA = (uint32_t)((warp_m * 64 + (lane & 15)) * ROWB +
                                     ((lane & 16) ? 16 : 0));
    const uint32_t offB = (uint32_t)((warp_n * 32 + (lane & 7) + ((lane & 16) ? 8 : 0)) * ROWB +
                                     ((lane & 8) ? 16 : 0));

    float acc[4][4][4];
#pragma unroll
    for (int i = 0; i < 4; i++)
#pragma unroll
        for (int j = 0; j < 4; j++)
#pragma unroll
            for (int k = 0; k < 4; k++) acc[i][j][k] = 0.f;

    load_stage(0, 0);
    load_stage(1, 1);

    const int NIT = DD / 32;
    int slot = 0;
    for (int it = 0; it < NIT; it++) {
        if (it + 1 < NIT) { CP_WAIT(1); } else { CP_WAIT(0); }
        __syncthreads();
        if (it + 2 < NIT) {
            int ns = slot + 2; if (ns >= 3) ns -= 3;
            load_stage(ns, it + 2);
        }
        const uint32_t base = sb + 1024 + slot * RT_STAGEB;
        const uint32_t Ah = base + 0 * MATB, Al = base + 1 * MATB;
        const uint32_t Bh = base + 2 * MATB, Bl = base + 3 * MATB;
#pragma unroll
        for (int kk = 0; kk < 2; kk++) {
            const uint32_t kof = kk * 32;
            uint32_t ah[4][4], al[4][4], bh[2][4], bl[2][4];
#pragma unroll
            for (int mf = 0; mf < 4; mf++) {
                const uint32_t o = offA + mf * 16 * ROWB + kof;
                ldsm4(ah[mf], Ah + o);
                ldsm4(al[mf], Al + o);
            }
#pragma unroll
            for (int nf2 = 0; nf2 < 2; nf2++) {
                const uint32_t o = offB + nf2 * 16 * ROWB + kof;
                ldsm4(bh[nf2], Bh + o);
                ldsm4(bl[nf2], Bl + o);
            }
#pragma unroll
            for (int mf = 0; mf < 4; mf++) {
#pragma unroll
                for (int nf = 0; nf < 4; nf++) {
                    const int n2 = nf >> 1, s = (nf & 1) * 2;
                    mma_fp16(acc[mf][nf], ah[mf], bh[n2][s], bh[n2][s + 1]);
                    mma_fp16(acc[mf][nf], ah[mf], bl[n2][s], bl[n2][s + 1]);
                    mma_fp16(acc[mf][nf], al[mf], bh[n2][s], bh[n2][s + 1]);
                }
            }
        }
        if (++slot == 3) slot = 0;
    }

    // epilogue: +bias, relu, store fp32 to g_hrelu
    const int g   = lane >> 2;
    const int tig = lane & 3;
#pragma unroll
    for (int mf = 0; mf < 4; mf++) {
        const int m0 = warp_m * 64 + mf * 16 + g;
        float* d0 = g_hrelu + ((size_t)l * TT + mt * 128 + m0) * RR;
        float* d1 = g_hrelu + ((size_t)l * TT + mt * 128 + m0 + 8) * RR;
#pragma unroll
        for (int nf = 0; nf < 4; nf++) {
            const int n = warp_n * 32 + nf * 8 + tig * 2;
            const float2 bv = *(const float2*)(b1 + l * RR + n);
            float2 o0, o1;
            o0.x = fmaxf(acc[mf][nf][0] + bv.x, 0.f);
            o0.y = fmaxf(acc[mf][nf][1] + bv.y, 0.f);
            o1.x = fmaxf(acc[mf][nf][2] + bv.x, 0.f);
            o1.y = fmaxf(acc[mf][nf][3] + bv.y, 0.f);
            *(float2*)(d0 + n) = o0;
            *(float2*)(d1 + n) = o1;
        }
    }
}

// =================================================================================
// logits / topk / copy (unchanged, validated)
// =================================================================================
__global__ void logits_kernel(const float* __restrict__ W2, const float* __restrict__ b2) {
    const int gw   = (blockIdx.x * blockDim.x + threadIdx.x) >> 5;
    const int lane = threadIdx.x & 31;
    const int l = gw >> 11;
    const int t = gw & 2047;
    const float* h = g_hrelu + ((size_t)l * TT + t) * RR;
    const float* w = W2 + l * RR;
    float s = 0.f;
#pragma unroll
    for (int r = 0; r < RR; r += 32) s += h[r + lane] * w[r + lane];
#pragma unroll
    for (int o = 16; o; o >>= 1) s += __shfl_xor_sync(0xffffffffu, s, o);
    if (lane == 0) g_logits[l * TT + t] = s + b2[l];
}

__global__ void topk_kernel() {
    __shared__ unsigned long long keys[2048];
    const int l = blockIdx.x;
    const int tid = threadIdx.x;
    for (int i = tid; i < 2048; i += 1024) {
        float f = g_logits[l * TT + i];
        unsigned u = __float_as_uint(f);
        u = (u & 0x80000000u) ? ~u : (u | 0x80000000u);
        keys[i] = ((unsigned long long)(~u) << 32) | (unsigned)i;
    }
    __syncthreads();
    for (int ks = 2; ks <= 2048; ks <<= 1) {
        for (int j = ks >> 1; j > 0; j >>= 1) {
            for (int i = tid; i < 2048; i += 1024) {
                int ixj = i ^ j;
                if (ixj > i) {
                    unsigned long long a = keys[i], b = keys[ixj];
                    bool asc = ((i & ks) == 0);
                    if ((a > b) == asc) { keys[i] = b; keys[ixj] = a; }
                }
            }
            __syncthreads();
        }
    }
    for (int i = tid; i < 2048; i += 1024) {
        int idx = (int)(keys[i] & 0xFFFFFFFFu);
        if (i < KK) g_copy_idx[l * KK + i]        = idx;
        else        g_comp_idx[l * KK + (i - KK)] = idx;
    }
}

__global__ void copy_s2_kernel(const float* __restrict__ s2, float* __restrict__ out) {
    const int l = blockIdx.y;
    const int t = g_copy_idx[l * KK + blockIdx.x];
    const float4* src = (const float4*)(s2  + ((size_t)l * TT + t) * DD);
    float4*       dst = (float4*)      (out + ((size_t)l * TT + t) * DD);
#pragma unroll
    for (int i = threadIdx.x; i < DD / 4; i += 256) dst[i] = src[i];
}

// =================================================================================
// s1 GEMM: 1-pass fp16, out = ah*bh. Dropped al*b (+1.47e-4 measured) and ah*bl
// (~same, independent) => predicted rel_err ~2.1e-4, 4.8x under threshold.
// 2 matrices per stage. grid (DD/128=16, KK/128=8, LL=16), 256 threads.
// =================================================================================
__global__ __launch_bounds__(256, 1)
void s1_mma_kernel(const float* __restrict__ bs1, float* __restrict__ out) {
    extern __shared__ __align__(128) char smem[];
    const uint32_t sb = smem_u32(smem);
    int* rows_s = (int*)smem;
    const int tid  = threadIdx.x;
    const int lane = tid & 31;
    const int wid  = tid >> 5;
    const int nt = blockIdx.x, mt = blockIdx.y, l = blockIdx.z;

    if (tid < 128) rows_s[tid] = g_comp_idx[l * KK + mt * 128 + tid];
    __syncthreads();

    const __half *pa_hi[2], *pb_hi[2];
    uint32_t sdst[2];
#pragma unroll
    for (int q = 0; q < 2; q++) {
        const int c   = tid + q * 256;
        const int row = c >> 2, ch = c & 3;
        const size_t aoff = ((size_t)l * TT + rows_s[row]) * DD + ch * 8;
        pa_hi[q] = g_hid_hi + aoff;
        const size_t boff = ((size_t)l * DD + nt * 128 + row) * DD + ch * 8;
        pb_hi[q] = g_wt_hi + boff;
        sdst[q] = (uint32_t)(row * ROWB + ch * 16);
    }

    auto load_stage = [&](int buf, int it) {
        const uint32_t base = sb + 1024 + buf * S1_STAGEB;
        const int ko = it * 32;
#pragma unroll
        for (int q = 0; q < 2; q++) {
            cp16(base + 0 * MATB + sdst[q], pa_hi[q] + ko);
            cp16(base + 1 * MATB + sdst[q], pb_hi[q] + ko);
        }
        CP_COMMIT();
    };

    const int warp_m = wid & 1;
    const int warp_n = wid >> 1;
    const uint32_t offA = (uint32_t)((warp_m * 64 + (lane & 15)) * ROWB +
                                     ((lane & 16) ? 16 : 0));
    const uint32_t offB = (uint32_t)((warp_n * 32 + (lane & 7) + ((lane & 16) ? 8 : 0)) * ROWB +
                                     ((lane & 8) ? 16 : 0));

    float acc[4][4][4];
#pragma unroll
    for (int i = 0; i < 4; i++)
#pragma unroll
        for (int j = 0; j < 4; j++)
#pragma unroll
            for (int k = 0; k < 4; k++) acc[i][j][k] = 0.f;

    load_stage(0, 0);
    load_stage(1, 1);

    const int NIT = DD / 32;
    int slot = 0;
    for (int it = 0; it < NIT; it++) {
        if (it + 1 < NIT) { CP_WAIT(1); } else { CP_WAIT(0); }
        __syncthreads();
        if (it + 2 < NIT) {
            int ns = slot + 2; if (ns >= 3) ns -= 3;
            load_stage(ns, it + 2);
        }
        const uint32_t base = sb + 1024 + slot * S1_STAGEB;
        const uint32_t Ah = base + 0 * MATB;
        const uint32_t Bh = base + 1 * MATB;
#pragma unroll
        for (int kk = 0; kk < 2; kk++) {
            const uint32_t kof = kk * 32;
            uint32_t ah[4][4], bh[2][4];
#pragma unroll
            for (int mf = 0; mf < 4; mf++)
                ldsm4(ah[mf], Ah + offA + mf * 16 * ROWB + kof);
#pragma unroll
            for (int nf2 = 0; nf2 < 2; nf2++)
                ldsm4(bh[nf2], Bh + offB + nf2 * 16 * ROWB + kof);
#pragma unroll
            for (int mf = 0; mf < 4; mf++) {
#pragma unroll
                for (int nf = 0; nf < 4; nf++) {
                    const int n2 = nf >> 1, s = (nf & 1) * 2;
                    mma_fp16(acc[mf][nf], ah[mf], bh[n2][s], bh[n2][s + 1]);
                }
            }
        }
        if (++slot == 3) slot = 0;
    }

    const int g   = lane >> 2;
    const int tig = lane & 3;
#pragma unroll
    for (int mf = 0; mf < 4; mf++) {
        const int m0 = warp_m * 64 + mf * 16 + g;
        const int r0 = rows_s[m0];
        const int r1 = rows_s[m0 + 8];
        float* d0 = out + ((size_t)l * TT + r0) * DD;
        float* d1 = out + ((size_t)l * TT + r1) * DD;
#pragma unroll
        for (int nf = 0; nf < 4; nf++) {
            const int n = nt * 128 + warp_n * 32 + nf * 8 + tig * 2;
            const float2 bv = *(const float2*)(bs1 + l * DD + n);
            float2 o0, o1;
            o0.x = acc[mf][nf][0] + bv.x; o0.y = acc[mf][nf][1] + bv.y;
            o1.x = acc[mf][nf][2] + bv.x; o1.y = acc[mf][nf][3] + bv.y;
            *(float2*)(d0 + n) = o0;
            *(float2*)(d1 + n) = o1;
        }
    }
}

// =================================================================================
extern "C" void kernel_launch(void* const* d_in, const int* in_sizes, int n_in,
                              void* d_out, int out_size) {
    const float* hidden = (const float*)d_in[0];
    const float* s2     = (const float*)d_in[1];
    const float* W_r1   = (const float*)d_in[2];
    const float* b_r1   = (const float*)d_in[3];
    const float* W_r2   = (const float*)d_in[4];
    const float* b_r2   = (const float*)d_in[5];
    const float* W_s1   = (const float*)d_in[6];
    const float* b_s1   = (const float*)d_in[7];
    float* out = (float*)d_out;

    static cudaStream_t sB = nullptr;
    static cudaEvent_t e0, eB, eT, eC;
    static bool init_done = false;
    if (!init_done) {
        cudaFuncSetAttribute(s1_mma_kernel,
                             cudaFuncAttributeMaxDynamicSharedMemorySize, S1_SMEM);
        cudaFuncSetAttribute(router_mma_kernel,
                             cudaFuncAttributeMaxDynamicSharedMemorySize, RT_SMEM);
        cudaStreamCreateWithFlags(&sB, cudaStreamNonBlocking);
        cudaEventCreateWithFlags(&e0, cudaEventDisableTiming);
        cudaEventCreateWithFlags(&eB, cudaEventDisableTiming);
        cudaEventCreateWithFlags(&eT, cudaEventDisableTiming);
        cudaEventCreateWithFlags(&eC, cudaEventDisableTiming);
        init_done = true;
    }

    // main stream: hidden split (needed by both branches)
    conv_hidden_kernel<<<(LL * TT * (DD / 4)) / 256, 256>>>(hidden);
    cudaEventRecord(e0, 0);

    // branch B: W_s1 transpose (only needed by s1)
    cudaStreamWaitEvent(sB, e0, 0);
    conv_wt_kernel<<<dim3(DD / 32, DD / 32, LL), dim3(32, 8), 0, sB>>>(W_s1);
    cudaEventRecord(eB, sB);

    // main stream: router chain
    conv_wr1_kernel<<<dim3(RR / 32, DD / 32, LL), dim3(32, 8)>>>(W_r1);
    router_mma_kernel<<<dim3(TT / 128, LL), 256, RT_SMEM>>>(b_r1);
    logits_kernel<<<(LL * TT) / 8, 256>>>(W_r2, b_r2);
    topk_kernel<<<LL, 1024>>>();
    cudaEventRecord(eT, 0);

    // branch B: copy top-K rows (needs topk only), overlapped with s1
    cudaStreamWaitEvent(sB, eT, 0);
    copy_s2_kernel<<<dim3(KK, LL), 256, 0, sB>>>(s2, out);
    cudaEventRecord(eC, sB);

    // main stream: s1 GEMM (needs conv_wt + topk)
    cudaStreamWaitEvent(0, eB, 0);
    dim3 g2(DD / 128, KK / 128, LL);
    s1_mma_kernel<<<g2, 256, S1_SMEM>>>(b_s1, out);
    cudaStreamWaitEvent(0, eC, 0);   // join copy branch
}